// round 9
// baseline (speedup 1.0000x reference)
#include <cuda_runtime.h>
#include <cuda_fp16.h>
#include <float.h>
#include <stdint.h>

#define NCODES   4096
#define CDIM     64
#define NTOK     65536
#define HW       4096
#define M_TILE   64
#define N_CHUNK  128
#define NCHUNKS  32
#define THREADS  256
#define SCALE    64.0f

#define B_STRIDE 144   // 64 halves (128B) + 16B pad -> conflict-free ldmatrix

// ---- smem byte offsets (per CTA total 108800 -> 2 CTAs/SM) ----
#define OFF_ZS     0        // 64*68*4 = 17408 fp32 z (scaled); reused as gather stage
#define OFF_ESQ    17408    // 16384
#define OFF_BH0    33792    // 18432
#define OFF_BL0    52224    // 18432
#define OFF_BH1    70656    // 18432
#define OFF_BL1    89088    // 18432 (ends 107520)
#define OFF_CANDV  107520   // 2*64 floats = 512
#define OFF_CANDI  108032   // 512
#define OFF_SIDX   108544   // 256
#define SMEM_TOTAL 108800

__device__ float  g_esq[NCODES];             // scaled by 4096
__device__ __half g_embh[NCODES * CDIM];     // hi(e*64)
__device__ __half g_embl[NCODES * CDIM];     // lo(e*64)

__device__ __forceinline__ uint32_t smem_u32(const void* p) {
    uint32_t a;
    asm("{ .reg .u64 t; cvta.to.shared.u64 t, %1; cvt.u32.u64 %0, t; }" : "=r"(a) : "l"(p));
    return a;
}
__device__ __forceinline__ void cp16(uint32_t dst, const void* src) {
    asm volatile("cp.async.cg.shared.global [%0], [%1], 16;" :: "r"(dst), "l"(src));
}
__device__ __forceinline__ void cp_commit() { asm volatile("cp.async.commit_group;"); }
template <int N>
__device__ __forceinline__ void cp_wait() { asm volatile("cp.async.wait_group %0;" :: "n"(N)); }

__device__ __forceinline__ void mma16816(float* c, const uint32_t* a, uint32_t b0, uint32_t b1) {
    asm volatile(
        "mma.sync.aligned.m16n8k16.row.col.f32.f16.f16.f32 "
        "{%0,%1,%2,%3}, {%4,%5,%6,%7}, {%8,%9}, {%0,%1,%2,%3};"
        : "+f"(c[0]), "+f"(c[1]), "+f"(c[2]), "+f"(c[3])
        : "r"(a[0]), "r"(a[1]), "r"(a[2]), "r"(a[3]), "r"(b0), "r"(b1));
}
__device__ __forceinline__ void ldmx4(uint32_t& r0, uint32_t& r1, uint32_t& r2, uint32_t& r3,
                                      uint32_t a) {
    asm volatile("ldmatrix.sync.aligned.m8n8.x4.shared.b16 {%0,%1,%2,%3}, [%4];"
        : "=r"(r0), "=r"(r1), "=r"(r2), "=r"(r3) : "r"(a));
}
__device__ __forceinline__ uint32_t pack2h(float v0, float v1) {
    __half h0 = __float2half_rn(v0);
    __half h1 = __float2half_rn(v1);
    return (uint32_t)__half_as_ushort(h0) | ((uint32_t)__half_as_ushort(h1) << 16);
}

// prep: hi/lo fp16 codebook (scaled by 64) + scaled ||e||^2. one warp per code.
__global__ void prep_kernel(const float* __restrict__ emb) {
    int warp = (blockIdx.x * blockDim.x + threadIdx.x) >> 5;
    int lane = threadIdx.x & 31;
    if (warp >= NCODES) return;
    const float* row = emb + (size_t)warp * CDIM;
    float v0 = row[lane] * SCALE, v1 = row[lane + 32] * SCALE;
    __half h0 = __float2half_rn(v0), h1 = __float2half_rn(v1);
    g_embh[warp * CDIM + lane]      = h0;
    g_embh[warp * CDIM + lane + 32] = h1;
    g_embl[warp * CDIM + lane]      = __float2half_rn(v0 - __half2float(h0));
    g_embl[warp * CDIM + lane + 32] = __float2half_rn(v1 - __half2float(h1));
    float s = v0 * v0 + v1 * v1;   // already scale^2 * ||e||^2
    #pragma unroll
    for (int off = 16; off; off >>= 1) s += __shfl_xor_sync(0xffffffffu, s, off);
    if (lane == 0) g_esq[warp] = s;
}

__global__ __launch_bounds__(THREADS, 2)
void vq_kernel(const float* __restrict__ z,
               const float* __restrict__ emb,
               float* __restrict__ out) {
    extern __shared__ char sm[];
    float* zs    = (float*)(sm + OFF_ZS);     // [64][68]
    float* esq_s = (float*)(sm + OFF_ESQ);    // [4096]
    float* candv = (float*)(sm + OFF_CANDV);  // [2][64]
    int*   candi = (int*)(sm + OFF_CANDI);
    int*   sidx  = (int*)(sm + OFF_SIDX);     // [64]

    const uint32_t sb = smem_u32(sm);
    const int tid  = threadIdx.x;
    const int lane = tid & 31;
    const int wid  = tid >> 5;
    const int grp  = lane >> 2;     // 0..7
    const int tid4 = lane & 3;      // 0..3
    const int mwarp = wid >> 1;     // 0..3 : token rows mwarp*16 + {grp, grp+8}
    const int nw    = wid & 1;      // 0..1 : code cols nw*64..+63 within chunk

    const int n0  = blockIdx.x * M_TILE;
    const int bb  = n0 >> 12;
    const int hw0 = n0 & (HW - 1);
    const float* zb = z + (size_t)bb * CDIM * HW + hw0;

    // ---- issue cp.async for chunk 0 (hi + lo) ----
    {
        #pragma unroll
        for (int t = 0; t < 8; t++) {
            int item = tid + 256 * t;
            int mat  = item >> 10;
            int row  = (item >> 3) & 127;
            int part = item & 7;
            const __half* src = (mat ? g_embl : g_embh) + row * 64 + part * 8;
            uint32_t dst = sb + (mat ? OFF_BL0 : OFF_BH0) + row * B_STRIDE + part * 16;
            cp16(dst, src);
        }
        cp_commit();
    }

    // ---- stage z (scaled) ----
    #pragma unroll
    for (int t = 0; t < 16; t++) {
        int i = tid + 256 * t;
        int c = i >> 6, tok = i & 63;
        zs[c * 68 + tok] = zb[(size_t)c * HW + tok] * SCALE;
    }
    // ---- esq (pre-scaled in prep) ----
    #pragma unroll
    for (int j = 0; j < 16; j++)
        esq_s[tid + j * 256] = g_esq[tid + j * 256];
    __syncthreads();

    // ---- A fragments (hi + lo) in registers: warp tile m16 ----
    uint32_t Ah[4][4], Al[4][4];
    {
        const int r0 = mwarp * 16 + grp;
        #pragma unroll
        for (int s = 0; s < 4; s++) {
            const int kb = 2 * tid4 + 16 * s;
            #pragma unroll
            for (int j = 0; j < 4; j++) {
                const int kk = kb + (j >> 1) * 8;
                const int rr = r0 + (j & 1) * 8;
                float v0 = zs[kk * 68 + rr];
                float v1 = zs[(kk + 1) * 68 + rr];
                __half h0 = __float2half_rn(v0), h1 = __float2half_rn(v1);
                Ah[s][j] = (uint32_t)__half_as_ushort(h0) | ((uint32_t)__half_as_ushort(h1) << 16);
                Al[s][j] = pack2h(v0 - __half2float(h0), v1 - __half2float(h1));
            }
        }
    }
    cp_wait<0>();
    __syncthreads();

    const int lrow  = (lane & 7) + ((lane >> 4) & 1) * 8;
    const int lkoff = ((lane >> 3) & 1) * 16;
    const uint32_t bladdr = (uint32_t)(nw * 64 + lrow) * B_STRIDE + lkoff;
    const uint32_t bh_off[2] = { OFF_BH0, OFF_BH1 };
    const uint32_t bl_off[2] = { OFF_BL0, OFF_BL1 };

    float best[2];
    int   bidx[2];
    best[0] = best[1] = FLT_MAX;
    bidx[0] = bidx[1] = 0;

    for (int ch = 0; ch < NCHUNKS; ch++) {
        const int buf = ch & 1;

        // issue next chunk into buf^1
        if (ch < NCHUNKS - 1) {
            const size_t cbase = (size_t)(ch + 1) * N_CHUNK * CDIM;
            #pragma unroll
            for (int t = 0; t < 8; t++) {
                int item = tid + 256 * t;
                int mat  = item >> 10;
                int row  = (item >> 3) & 127;
                int part = item & 7;
                const __half* src = (mat ? g_embl : g_embh) + cbase + row * 64 + part * 8;
                uint32_t dst = sb + (mat ? bl_off[buf ^ 1] : bh_off[buf ^ 1]) + row * B_STRIDE + part * 16;
                cp16(dst, src);
            }
            cp_commit();
        }

        float acc[8][4];
        #pragma unroll
        for (int f = 0; f < 8; f++)
            #pragma unroll
            for (int r = 0; r < 4; r++) acc[f][r] = 0.f;

        const uint32_t bhb = sb + bh_off[buf] + bladdr;
        const uint32_t blb = sb + bl_off[buf] + bladdr;

        // ---- pass-major MMA schedule: same-acc chain distance = 8 issues ----
        #pragma unroll
        for (int s = 0; s < 4; s++) {
            uint32_t BH[4][4], BL[4][4];
            #pragma unroll
            for (int fp = 0; fp < 4; fp++)
                ldmx4(BH[fp][0], BH[fp][1], BH[fp][2], BH[fp][3],
                      bhb + fp * (16 * B_STRIDE) + s * 32);
            // hi * hi  (f0..f7)
            #pragma unroll
            for (int fp = 0; fp < 4; fp++) {
                mma16816(acc[2 * fp],     Ah[s], BH[fp][0], BH[fp][1]);
                mma16816(acc[2 * fp + 1], Ah[s], BH[fp][2], BH[fp][3]);
            }
            #pragma unroll
            for (int fp = 0; fp < 4; fp++)
                ldmx4(BL[fp][0], BL[fp][1], BL[fp][2], BL[fp][3],
                      blb + fp * (16 * B_STRIDE) + s * 32);
            // lo * hi  (f0..f7, reuses BH)
            #pragma unroll
            for (int fp = 0; fp < 4; fp++) {
                mma16816(acc[2 * fp],     Al[s], BH[fp][0], BH[fp][1]);
                mma16816(acc[2 * fp + 1], Al[s], BH[fp][2], BH[fp][3]);
            }
            // hi * lo  (f0..f7)
            #pragma unroll
            for (int fp = 0; fp < 4; fp++) {
                mma16816(acc[2 * fp],     Ah[s], BL[fp][0], BL[fp][1]);
                mma16816(acc[2 * fp + 1], Ah[s], BL[fp][2], BL[fp][3]);
            }
        }

        // ---- epilogue: min-tree + rare rescan (exact, first-min tiebreak) ----
        const int cb = ch * N_CHUNK + nw * 64;
        float2 ee[8];
        #pragma unroll
        for (int f = 0; f < 8; f++)
            ee[f] = *(const float2*)&esq_s[cb + f * 8 + 2 * tid4];

        #pragma unroll
        for (int g = 0; g < 2; g++) {   // g=0 -> row grp; g=1 -> row grp+8
            float sv[16];
            #pragma unroll
            for (int f = 0; f < 8; f++) {
                sv[2 * f]     = fmaf(acc[f][g * 2 + 0], -2.0f, ee[f].x);
                sv[2 * f + 1] = fmaf(acc[f][g * 2 + 1], -2.0f, ee[f].y);
            }
            float mn = sv[0];
            #pragma unroll
            for (int j = 1; j < 16; j++) mn = fminf(mn, sv[j]);
            if (mn < best[g]) {
                best[g] = mn;
                int found = -1;
                #pragma unroll
                for (int j = 0; j < 16; j++)
                    if (found < 0 && sv[j] == mn)
                        found = cb + (j >> 1) * 8 + 2 * tid4 + (j & 1);
                bidx[g] = found;
            }
        }

        cp_wait<0>();
        __syncthreads();
    }

    // ---- reduce over tid4 quad (codes), then over nw via smem ----
    #pragma unroll
    for (int g = 0; g < 2; g++) {
        float v  = best[g];
        int   id = bidx[g];
        #pragma unroll
        for (int off = 1; off <= 2; off <<= 1) {
            float ov = __shfl_xor_sync(0xffffffffu, v, off);
            int   oi = __shfl_xor_sync(0xffffffffu, id, off);
            if (ov < v || (ov == v && oi < id)) { v = ov; id = oi; }
        }
        if (tid4 == 0) {
            int token = mwarp * 16 + g * 8 + grp;
            candv[nw * 64 + token] = v;
            candi[nw * 64 + token] = id;
        }
    }
    __syncthreads();
    if (tid < 64) {
        float v0 = candv[tid], v1 = candv[64 + tid];
        int   i0 = candi[tid], i1 = candi[64 + tid];
        sidx[tid] = (v1 < v0 || (v1 == v0 && i1 < i0)) ? i1 : i0;
    }
    __syncthreads();

    // ---- gather emb[idx], transposed coalesced write (stage in zs region) ----
    float* st = zs;   // [64][65]
    #pragma unroll
    for (int t = 0; t < 16; t++) {
        int i = tid + 256 * t;
        int tok = i >> 6, c = i & 63;
        st[tok * 65 + c] = emb[(size_t)sidx[tok] * CDIM + c];
    }
    __syncthreads();
    float* ob = out + (size_t)bb * CDIM * HW + hw0;
    #pragma unroll
    for (int t = 0; t < 16; t++) {
        int i = tid + 256 * t;
        int c = i >> 6, tok = i & 63;
        ob[(size_t)c * HW + tok] = st[tok * 65 + c];
    }
}

extern "C" void kernel_launch(void* const* d_in, const int* in_sizes, int n_in,
                              void* d_out, int out_size) {
    const float* z   = (const float*)d_in[0];
    const float* emb = (const float*)d_in[1];
    float* out = (float*)d_out;

    cudaFuncSetAttribute(vq_kernel, cudaFuncAttributeMaxDynamicSharedMemorySize, SMEM_TOTAL);

    prep_kernel<<<NCODES / 8, 256>>>(emb);
    vq_kernel<<<NTOK / M_TILE, THREADS, SMEM_TOTAL>>>(z, emb, out);
}

// round 10
// speedup vs baseline: 1.4736x; 1.4736x over previous
#include <cuda_runtime.h>
#include <cuda_fp16.h>
#include <float.h>
#include <stdint.h>

#define NCODES   4096
#define CDIM     64
#define NTOK     65536
#define HW       4096
#define M_TILE   128
#define N_CHUNK  128
#define NCHUNKS  32
#define THREADS  256
#define SCALE    64.0f

#define B_STRIDE 144      // 64 halves (128B) + 16B pad -> conflict-free ldmatrix
#define B_BUF    18944    // 128*144 B tile + 512B esq tail
#define ESQ_TAIL 18432

// ---- smem byte offsets (per CTA total 109568 -> 2 CTAs/SM) ----
#define OFF_ZS     0        // 64*130*4 = 33280 fp32 z (scaled); reused as gather stage [128][65]
#define OFF_BH0    33280
#define OFF_BL0    52224
#define OFF_BH1    71168
#define OFF_BL1    90112    // ends 109056
#define OFF_SIDX   109056   // 128 ints
#define SMEM_TOTAL 109568

__device__ float  g_esq[NCODES];             // scaled by 4096
__device__ __half g_embh[NCODES * CDIM];     // hi(e*64)
__device__ __half g_embl[NCODES * CDIM];     // lo(e*64)

__device__ __forceinline__ uint32_t smem_u32(const void* p) {
    uint32_t a;
    asm("{ .reg .u64 t; cvta.to.shared.u64 t, %1; cvt.u32.u64 %0, t; }" : "=r"(a) : "l"(p));
    return a;
}
__device__ __forceinline__ void cp16(uint32_t dst, const void* src) {
    asm volatile("cp.async.cg.shared.global [%0], [%1], 16;" :: "r"(dst), "l"(src));
}
__device__ __forceinline__ void cp_commit() { asm volatile("cp.async.commit_group;"); }
template <int N>
__device__ __forceinline__ void cp_wait() { asm volatile("cp.async.wait_group %0;" :: "n"(N)); }

__device__ __forceinline__ void mma16816(float* c, const uint32_t* a, uint32_t b0, uint32_t b1) {
    asm volatile(
        "mma.sync.aligned.m16n8k16.row.col.f32.f16.f16.f32 "
        "{%0,%1,%2,%3}, {%4,%5,%6,%7}, {%8,%9}, {%0,%1,%2,%3};"
        : "+f"(c[0]), "+f"(c[1]), "+f"(c[2]), "+f"(c[3])
        : "r"(a[0]), "r"(a[1]), "r"(a[2]), "r"(a[3]), "r"(b0), "r"(b1));
}
__device__ __forceinline__ void ldmx4(uint32_t& r0, uint32_t& r1, uint32_t& r2, uint32_t& r3,
                                      uint32_t a) {
    asm volatile("ldmatrix.sync.aligned.m8n8.x4.shared.b16 {%0,%1,%2,%3}, [%4];"
        : "=r"(r0), "=r"(r1), "=r"(r2), "=r"(r3) : "r"(a));
}
__device__ __forceinline__ uint32_t pack2h(float v0, float v1) {
    __half h0 = __float2half_rn(v0);
    __half h1 = __float2half_rn(v1);
    return (uint32_t)__half_as_ushort(h0) | ((uint32_t)__half_as_ushort(h1) << 16);
}

// prep: hi/lo fp16 codebook (scaled by 64) + scaled ||e||^2. one warp per code.
__global__ void prep_kernel(const float* __restrict__ emb) {
    int warp = (blockIdx.x * blockDim.x + threadIdx.x) >> 5;
    int lane = threadIdx.x & 31;
    if (warp >= NCODES) return;
    const float* row = emb + (size_t)warp * CDIM;
    float v0 = row[lane] * SCALE, v1 = row[lane + 32] * SCALE;
    __half h0 = __float2half_rn(v0), h1 = __float2half_rn(v1);
    g_embh[warp * CDIM + lane]      = h0;
    g_embh[warp * CDIM + lane + 32] = h1;
    g_embl[warp * CDIM + lane]      = __float2half_rn(v0 - __half2float(h0));
    g_embl[warp * CDIM + lane + 32] = __float2half_rn(v1 - __half2float(h1));
    float s = v0 * v0 + v1 * v1;   // scale^2 * ||e||^2
    #pragma unroll
    for (int off = 16; off; off >>= 1) s += __shfl_xor_sync(0xffffffffu, s, off);
    if (lane == 0) g_esq[warp] = s;
}

__global__ __launch_bounds__(THREADS, 2)
void vq_kernel(const float* __restrict__ z,
               const float* __restrict__ emb,
               float* __restrict__ out) {
    extern __shared__ char sm[];
    float* zs   = (float*)(sm + OFF_ZS);     // [64][130]
    int*   sidx = (int*)(sm + OFF_SIDX);     // [128]

    const uint32_t sb = smem_u32(sm);
    const int tid  = threadIdx.x;
    const int lane = tid & 31;
    const int wid  = tid >> 5;      // 0..7 : token rows wid*16 + {grp, grp+8}
    const int grp  = lane >> 2;     // 0..7
    const int tid4 = lane & 3;      // 0..3

    const int n0  = blockIdx.x * M_TILE;
    const int bb  = n0 >> 12;
    const int hw0 = n0 & (HW - 1);
    const float* zb = z + (size_t)bb * CDIM * HW + hw0;

    const uint32_t bh_off[2] = { OFF_BH0, OFF_BH1 };
    const uint32_t bl_off[2] = { OFF_BL0, OFF_BL1 };

    // ---- issue cp.async for chunk 0 (hi + lo + esq tail) ----
    {
        #pragma unroll
        for (int t = 0; t < 8; t++) {
            int item = tid + 256 * t;
            int mat  = item >> 10;              // 0: hi, 1: lo
            int row  = (item >> 3) & 127;
            int part = item & 7;
            const __half* src = (mat ? g_embl : g_embh) + row * 64 + part * 8;
            uint32_t dst = sb + (mat ? OFF_BL0 : OFF_BH0) + row * B_STRIDE + part * 16;
            cp16(dst, src);
        }
        if (tid < 32)
            cp16(sb + OFF_BH0 + ESQ_TAIL + tid * 16, g_esq + tid * 4);
        cp_commit();
    }

    // ---- stage z (scaled) ----
    #pragma unroll
    for (int t = 0; t < 32; t++) {
        int i = tid + 256 * t;
        int c = i >> 7, tok = i & 127;
        zs[c * 130 + tok] = zb[(size_t)c * HW + tok] * SCALE;
    }
    __syncthreads();

    // ---- A fragments (hi + lo) in registers: warp tile m16 ----
    uint32_t Ah[4][4], Al[4][4];
    {
        const int r0 = wid * 16 + grp;
        #pragma unroll
        for (int s = 0; s < 4; s++) {
            const int kb = 2 * tid4 + 16 * s;
            #pragma unroll
            for (int j = 0; j < 4; j++) {
                const int kk = kb + (j >> 1) * 8;
                const int rr = r0 + (j & 1) * 8;
                float v0 = zs[kk * 130 + rr];
                float v1 = zs[(kk + 1) * 130 + rr];
                __half h0 = __float2half_rn(v0), h1 = __float2half_rn(v1);
                Ah[s][j] = (uint32_t)__half_as_ushort(h0) | ((uint32_t)__half_as_ushort(h1) << 16);
                Al[s][j] = pack2h(v0 - __half2float(h0), v1 - __half2float(h1));
            }
        }
    }
    cp_wait<0>();
    __syncthreads();

    const int lrow  = (lane & 7) + ((lane >> 4) & 1) * 8;
    const int lkoff = ((lane >> 3) & 1) * 16;

    float best[2];
    int   bidx[2];
    best[0] = best[1] = FLT_MAX;
    bidx[0] = bidx[1] = 0;

    for (int ch = 0; ch < NCHUNKS; ch++) {
        const int buf = ch & 1;

        // issue next chunk into buf^1
        if (ch < NCHUNKS - 1) {
            const size_t cbase = (size_t)(ch + 1) * N_CHUNK * CDIM;
            #pragma unroll
            for (int t = 0; t < 8; t++) {
                int item = tid + 256 * t;
                int mat  = item >> 10;
                int row  = (item >> 3) & 127;
                int part = item & 7;
                const __half* src = (mat ? g_embl : g_embh) + cbase + row * 64 + part * 8;
                uint32_t dst = sb + (mat ? bl_off[buf ^ 1] : bh_off[buf ^ 1]) + row * B_STRIDE + part * 16;
                cp16(dst, src);
            }
            if (tid < 32)
                cp16(sb + bh_off[buf ^ 1] + ESQ_TAIL + tid * 16,
                     g_esq + (ch + 1) * N_CHUNK + tid * 4);
            cp_commit();
        }

        const float* esq_t = (const float*)(sm + bh_off[buf] + ESQ_TAIL);

        // ---- two n64 halves per chunk, R8-identical inner structure ----
        #pragma unroll
        for (int half = 0; half < 2; half++) {
            const uint32_t bladdr = (uint32_t)(half * 64 + lrow) * B_STRIDE + lkoff;
            const uint32_t bhb = sb + bh_off[buf] + bladdr;
            const uint32_t blb = sb + bl_off[buf] + bladdr;

            float acc[8][4];
            #pragma unroll
            for (int f = 0; f < 8; f++)
                #pragma unroll
                for (int r = 0; r < 4; r++) acc[f][r] = 0.f;

            #pragma unroll
            for (int s = 0; s < 4; s++) {
                #pragma unroll
                for (int fp = 0; fp < 4; fp++) {
                    uint32_t h0, h1, h2, h3, L0, L1, L2, L3;
                    ldmx4(h0, h1, h2, h3, bhb + fp * (16 * B_STRIDE) + s * 32);
                    ldmx4(L0, L1, L2, L3, blb + fp * (16 * B_STRIDE) + s * 32);
                    const int f0 = 2 * fp, f1 = 2 * fp + 1;
                    mma16816(acc[f0], Ah[s], h0, h1);   // hi*hi
                    mma16816(acc[f1], Ah[s], h2, h3);
                    mma16816(acc[f0], Ah[s], L0, L1);   // hi*lo
                    mma16816(acc[f1], Ah[s], L2, L3);
                    mma16816(acc[f0], Al[s], h0, h1);   // lo*hi
                    mma16816(acc[f1], Al[s], h2, h3);
                }
            }

            // ---- epilogue: min-tree + rare rescan (exact, first-min tiebreak) ----
            const int cb = ch * N_CHUNK + half * 64;
            float2 ee[8];
            #pragma unroll
            for (int f = 0; f < 8; f++)
                ee[f] = *(const float2*)&esq_t[half * 64 + f * 8 + 2 * tid4];

            #pragma unroll
            for (int g = 0; g < 2; g++) {   // g=0 -> row grp; g=1 -> row grp+8
                float sv[16];
                #pragma unroll
                for (int f = 0; f < 8; f++) {
                    sv[2 * f]     = fmaf(acc[f][g * 2 + 0], -2.0f, ee[f].x);
                    sv[2 * f + 1] = fmaf(acc[f][g * 2 + 1], -2.0f, ee[f].y);
                }
                float mn = sv[0];
                #pragma unroll
                for (int j = 1; j < 16; j++) mn = fminf(mn, sv[j]);
                if (mn < best[g]) {
                    best[g] = mn;
                    int found = -1;
                    #pragma unroll
                    for (int j = 0; j < 16; j++)
                        if (found < 0 && sv[j] == mn)
                            found = cb + (j >> 1) * 8 + 2 * tid4 + (j & 1);
                    bidx[g] = found;
                }
            }
        }

        cp_wait<0>();
        __syncthreads();
    }

    // ---- reduce over tid4 quad (codes); each warp owns its tokens ----
    #pragma unroll
    for (int g = 0; g < 2; g++) {
        float v  = best[g];
        int   id = bidx[g];
        #pragma unroll
        for (int off = 1; off <= 2; off <<= 1) {
            float ov = __shfl_xor_sync(0xffffffffu, v, off);
            int   oi = __shfl_xor_sync(0xffffffffu, id, off);
            if (ov < v || (ov == v && oi < id)) { v = ov; id = oi; }
        }
        if (tid4 == 0)
            sidx[wid * 16 + g * 8 + grp] = id;
    }
    __syncthreads();

    // ---- gather emb[idx], transposed coalesced write (stage in zs region) ----
    float* st = zs;   // [128][65]
    #pragma unroll
    for (int t = 0; t < 32; t++) {
        int i = tid + 256 * t;
        int tok = i >> 6, c = i & 63;
        st[tok * 65 + c] = emb[(size_t)sidx[tok] * CDIM + c];
    }
    __syncthreads();
    float* ob = out + (size_t)bb * CDIM * HW + hw0;
    #pragma unroll
    for (int t = 0; t < 32; t++) {
        int i = tid + 256 * t;
        int c = i >> 7, tok = i & 127;
        ob[(size_t)c * HW + tok] = st[tok * 65 + c];
    }
}

extern "C" void kernel_launch(void* const* d_in, const int* in_sizes, int n_in,
                              void* d_out, int out_size) {
    const float* z   = (const float*)d_in[0];
    const float* emb = (const float*)d_in[1];
    float* out = (float*)d_out;

    cudaFuncSetAttribute(vq_kernel, cudaFuncAttributeMaxDynamicSharedMemorySize, SMEM_TOTAL);

    prep_kernel<<<NCODES / 8, 256>>>(emb);
    vq_kernel<<<NTOK / M_TILE, THREADS, SMEM_TOTAL>>>(z, emb, out);
}